// round 13
// baseline (speedup 1.0000x reference)
#include <cuda_runtime.h>
#include <cstddef>

#define THREADS 128
#define GPB 8             // graphs per block, one per 16-lane group

// Output layout: concat of recon[B,4,13,13], mu[B,13,16], logvar[B,13,16] (fp32)
#define R_MU 22151168ull
#define R_LV 28966912ull

typedef unsigned long long u64;

__device__ __forceinline__ void ffma2(u64 &d, u64 a, u64 b) {
    asm("fma.rn.f32x2 %0, %1, %2, %0;" : "+l"(d) : "l"(a), "l"(b));
}
__device__ __forceinline__ u64 pack2(float lo, float hi) {
    u64 r; asm("mov.b64 %0, {%1, %2};" : "=l"(r) : "f"(lo), "f"(hi)); return r;
}
__device__ __forceinline__ float2 unpack2(u64 v) {
    float2 r; asm("mov.b64 {%0, %1}, %2;" : "=f"(r.x), "=f"(r.y) : "l"(v)); return r;
}
__device__ __forceinline__ float leaky(float v) { return v >= 0.f ? v : 0.01f * v; }
__device__ __forceinline__ u64 plo(float4 w) { return pack2(w.x, w.y); }
__device__ __forceinline__ u64 phi(float4 w) { return pack2(w.z, w.w); }

// 16-wide dot, 2 accumulator chains
__device__ __forceinline__ float dot16s(const u64* pw, const u64* a2) {
    u64 accA = 0ull, accB = 0ull;
#pragma unroll
    for (int q = 0; q < 4; q++) ffma2(accA, a2[q],     pw[q]);
#pragma unroll
    for (int q = 0; q < 4; q++) ffma2(accB, a2[q + 4], pw[q + 4]);
    float2 fa = unpack2(accA), fb = unpack2(accB);
    return (fa.x + fb.x) + (fa.y + fb.y);
}

// Hot mainloop weights on the constant port (3 memcpy nodes per launch)
struct __align__(16) CParams {
    float4 w0[256];      // mlp_w0  [l][e][4]
    float4 w1[256];      // mlp_w1
    float4 dec[256];     // dec_w   [k][d][4]
};
__constant__ CParams cp;

struct __align__(16) Smem {
    float  adj[GPB * 676];     // staging for reg fill; reused as recon staging
    float4 xsv[GPB * 65];      // per-g node rows, pitch 5 float4
};

__global__ __launch_bounds__(THREADS, 4) void vae_fused(
    const float* __restrict__ adj,
    const float* __restrict__ init_weight,
    const float* __restrict__ eps_param,
    const float* __restrict__ mlp_b0, const float* __restrict__ mlp_b1,
    const float* __restrict__ bn_in_gamma,  const float* __restrict__ bn_in_beta,
    const float* __restrict__ bn_in_mean,   const float* __restrict__ bn_in_var,
    const float* __restrict__ bn_out_gamma, const float* __restrict__ bn_out_beta,
    const float* __restrict__ bn_out_mean,  const float* __restrict__ bn_out_var,
    const float* __restrict__ fc1_w, const float* __restrict__ fc1_b,
    const float* __restrict__ fc2_w, const float* __restrict__ fc2_b,
    const float* __restrict__ dec_b,
    float* __restrict__ out)
{
    extern __shared__ Smem sm[];
    Smem& s = sm[0];
    const int tid = threadIdx.x;

    {   // adj for this block's graphs (contiguous float4) -> SMEM (coalesced)
        const float4* src = (const float4*)(adj + (size_t)blockIdx.x * (GPB * 676));
        float4* dst = (float4*)s.adj;
        for (int i = tid; i < GPB * 169; i += THREADS) dst[i] = src[i];
    }
    __syncthreads();

    const int grp = tid >> 4;          // 0..7
    const int n   = tid & 15;          // node; lanes 13..15 idle for compute
    const size_t b = (size_t)blockIdx.x * GPB + grp;
    const float* ad = s.adj + grp * 676;
    float4*      xp = s.xsv + grp * 65;
    const bool act = (n < 13);
    const int nn = act ? n : 0;

    // ---- hoist this thread's adjacency rows into registers (loop-invariant) ----
    float adjr[52];                    // [i*13 + m]
    if (act) {
#pragma unroll
        for (int i = 0; i < 4; i++)
#pragma unroll
            for (int m = 0; m < 13; m++)
                adjr[i*13 + m] = ad[i*169 + n*13 + m];
    } else {
#pragma unroll
        for (int q = 0; q < 52; q++) adjr[q] = 0.f;
    }

    float x[16];

    // ---- init: x[n,:] = sum_m (sum_i adj[i,n,m]) * W[m,:]
    if (act) {
        u64 x2[8];
#pragma unroll
        for (int q = 0; q < 8; q++) x2[q] = 0ull;
#pragma unroll
        for (int m = 0; m < 13; m++) {
            float as = adjr[m] + adjr[13 + m] + adjr[26 + m] + adjr[39 + m];
            const float4* wr = (const float4*)init_weight + m * 4;
            float4 w0_ = __ldg(wr), w1_ = __ldg(wr+1), w2_ = __ldg(wr+2), w3_ = __ldg(wr+3);
            u64 a = pack2(as, as);
            ffma2(x2[0], a, plo(w0_)); ffma2(x2[1], a, phi(w0_));
            ffma2(x2[2], a, plo(w1_)); ffma2(x2[3], a, phi(w1_));
            ffma2(x2[4], a, plo(w2_)); ffma2(x2[5], a, phi(w2_));
            ffma2(x2[6], a, plo(w3_)); ffma2(x2[7], a, phi(w3_));
        }
#pragma unroll
        for (int q = 0; q < 8; q++) { float2 f = unpack2(x2[q]); x[2*q] = f.x; x[2*q+1] = f.y; }
#pragma unroll
        for (int q = 0; q < 4; q++)
            xp[n*5 + q] = make_float4(x[4*q], x[4*q+1], x[4*q+2], x[4*q+3]);
    }
    __syncwarp();

    // ---- 4 GIN layers ----
#pragma unroll 1
    for (int l = 0; l < 4; l++) {
        const int pi = l * 13 + nn;
        const float si = __ldg(bn_in_gamma + pi)  * rsqrtf(__ldg(bn_in_var + pi)  + 1e-5f);
        const float ti = __ldg(bn_in_beta + pi)   - __ldg(bn_in_mean + pi)  * si;
        const float so = __ldg(bn_out_gamma + pi) * rsqrtf(__ldg(bn_out_var + pi) + 1e-5f);
        const float to = __ldg(bn_out_beta + pi)  - __ldg(bn_out_mean + pi) * so;
        if (act) {
            const float ep = 1.f + __ldg(eps_param + l);
            u64 agg2[8];
#pragma unroll
            for (int q = 0; q < 8; q++) agg2[q] = pack2(ep * x[2*q], ep * x[2*q+1]);
#pragma unroll
            for (int i = 0; i < 4; i++) {
#pragma unroll
                for (int m = 0; m < 13; m++) {
                    float av = adjr[i*13 + m];
                    u64 a = pack2(av, av);
                    float4 xr = xp[m*5 + i];
                    ffma2(agg2[2*i],     a, plo(xr));
                    ffma2(agg2[2*i + 1], a, phi(xr));
                }
            }
            float h1[16];
#pragma unroll
            for (int e = 0; e < 16; e++) {
                float4 wa = cp.w0[l*64 + e*4],     wb = cp.w0[l*64 + e*4 + 1];
                float4 wc = cp.w0[l*64 + e*4 + 2], wd = cp.w0[l*64 + e*4 + 3];
                u64 pw[8] = { plo(wa), phi(wa), plo(wb), phi(wb),
                              plo(wc), phi(wc), plo(wd), phi(wd) };
                float bb = __ldg(mlp_b0 + l*16 + e);
                h1[e] = leaky(si * (dot16s(pw, agg2) + bb) + ti);
            }
            u64 h2[8];
#pragma unroll
            for (int q = 0; q < 8; q++) h2[q] = pack2(h1[2*q], h1[2*q+1]);
#pragma unroll
            for (int e = 0; e < 16; e++) {
                float4 wa = cp.w1[l*64 + e*4],     wb = cp.w1[l*64 + e*4 + 1];
                float4 wc = cp.w1[l*64 + e*4 + 2], wd = cp.w1[l*64 + e*4 + 3];
                u64 pw[8] = { plo(wa), phi(wa), plo(wb), phi(wb),
                              plo(wc), phi(wc), plo(wd), phi(wd) };
                float bb = __ldg(mlp_b1 + l*16 + e);
                x[e] = leaky(so * (dot16s(pw, h2) + bb) + to);
            }
        }
        __syncwarp();
        if (act) {
#pragma unroll
            for (int q = 0; q < 4; q++)
                xp[n*5 + q] = make_float4(x[4*q], x[4*q+1], x[4*q+2], x[4*q+3]);
        }
        __syncwarp();
    }

    // ---- heads: mu / logvar (direct STG.128 writes) ----
    float mu[16];
    if (act) {
        float lv[16];
        u64 x2[8];
#pragma unroll
        for (int q = 0; q < 8; q++) x2[q] = pack2(x[2*q], x[2*q+1]);
#pragma unroll
        for (int e = 0; e < 16; e++) {
            const float4* r1 = (const float4*)fc1_w + e*4;
            const float4* r2 = (const float4*)fc2_w + e*4;
            float4 a1 = __ldg(r1), b1_ = __ldg(r1+1), c1 = __ldg(r1+2), d1 = __ldg(r1+3);
            float4 a2 = __ldg(r2), b2_ = __ldg(r2+1), c2 = __ldg(r2+2), d2 = __ldg(r2+3);
            u64 p1[8] = { plo(a1), phi(a1), plo(b1_), phi(b1_), plo(c1), phi(c1), plo(d1), phi(d1) };
            u64 p2[8] = { plo(a2), phi(a2), plo(b2_), phi(b2_), plo(c2), phi(c2), plo(d2), phi(d2) };
            mu[e] = dot16s(p1, x2) + __ldg(fc1_b + e);
            lv[e] = dot16s(p2, x2) + __ldg(fc2_b + e);
        }
        const size_t moff = b * 208 + (size_t)n * 16;
        float4* mo = (float4*)(out + R_MU + moff);
        float4* lo = (float4*)(out + R_LV + moff);
#pragma unroll
        for (int q = 0; q < 4; q++) {
            mo[q] = make_float4(mu[4*q], mu[4*q+1], mu[4*q+2], mu[4*q+3]);
            lo[q] = make_float4(lv[4*q], lv[4*q+1], lv[4*q+2], lv[4*q+3]);
        }
    }

    // ---- decoder: recon staged into the (dead) adj slice, then coalesced out ----
    u64 mu2[8];
    if (act) {
#pragma unroll
        for (int q = 0; q < 8; q++) mu2[q] = pack2(mu[2*q], mu[2*q+1]);
    }
    float* rec = (float*)ad;            // 676 floats, 16B-aligned

#pragma unroll 1
    for (int k = 0; k < 4; k++) {
        __syncwarp();
        float t[16];
        if (act) {
#pragma unroll
            for (int d = 0; d < 16; d++) {
                float4 wa = cp.dec[k*64 + d*4],     wb = cp.dec[k*64 + d*4 + 1];
                float4 wc = cp.dec[k*64 + d*4 + 2], wd = cp.dec[k*64 + d*4 + 3];
                u64 pw[8] = { plo(wa), phi(wa), plo(wb), phi(wb),
                              plo(wc), phi(wc), plo(wd), phi(wd) };
                t[d] = dot16s(pw, mu2) + __ldg(dec_b + k*16 + d);
            }
#pragma unroll
            for (int q = 0; q < 4; q++)
                xp[n*5 + q] = make_float4(t[4*q], t[4*q+1], t[4*q+2], t[4*q+3]);
        }
        __syncwarp();
        if (act) {
            u64 t2[8];
#pragma unroll
            for (int q = 0; q < 8; q++) t2[q] = pack2(t[2*q], t[2*q+1]);
            float* rr = rec + k * 169 + n * 13;
#pragma unroll
            for (int m = 0; m < 13; m++) {
                u64 accA = 0ull, accB = 0ull;
#pragma unroll
                for (int q = 0; q < 2; q++) {
                    float4 xr = xp[m*5 + q];
                    ffma2(accA, t2[2*q],     plo(xr));
                    ffma2(accA, t2[2*q + 1], phi(xr));
                }
#pragma unroll
                for (int q = 2; q < 4; q++) {
                    float4 xr = xp[m*5 + q];
                    ffma2(accB, t2[2*q],     plo(xr));
                    ffma2(accB, t2[2*q + 1], phi(xr));
                }
                float2 fa = unpack2(accA), fb = unpack2(accB);
                float sv = (fa.x + fb.x) + (fa.y + fb.y);
                rr[m] = sv > 0.f ? sv : 0.f;
            }
        }
    }
    __syncwarp();
    // coalesced recon writeout: 676 floats = 169 float4
    {
        const float4* r4 = (const float4*)rec;
        float4* o4 = (float4*)(out + b * 676);
#pragma unroll
        for (int it = 0; it < 11; it++) {
            int idx = it * 16 + n;               // 0..175, need 0..168
            if (idx < 169) o4[idx] = r4[idx];
        }
    }
}

extern "C" void kernel_launch(void* const* d_in, const int* in_sizes, int n_in,
                              void* d_out, int out_size) {
    (void)in_sizes; (void)n_in; (void)out_size;

    // Hot weights -> constant memory (D2D, graph-capturable)
    cudaMemcpyToSymbolAsync(cp, d_in[3],  4096, offsetof(CParams, w0),  cudaMemcpyDeviceToDevice);
    cudaMemcpyToSymbolAsync(cp, d_in[5],  4096, offsetof(CParams, w1),  cudaMemcpyDeviceToDevice);
    cudaMemcpyToSymbolAsync(cp, d_in[19], 4096, offsetof(CParams, dec), cudaMemcpyDeviceToDevice);

    cudaFuncSetAttribute(vae_fused, cudaFuncAttributeMaxDynamicSharedMemorySize,
                         (int)sizeof(Smem));
    vae_fused<<<32768 / GPB, THREADS, sizeof(Smem)>>>(
        (const float*)d_in[0],  (const float*)d_in[1],  (const float*)d_in[2],
        (const float*)d_in[4],  (const float*)d_in[6],
        (const float*)d_in[7],  (const float*)d_in[8],
        (const float*)d_in[9],  (const float*)d_in[10],
        (const float*)d_in[11], (const float*)d_in[12],
        (const float*)d_in[13], (const float*)d_in[14],
        (const float*)d_in[15], (const float*)d_in[16],
        (const float*)d_in[17], (const float*)d_in[18],
        (const float*)d_in[20],
        (float*)d_out);
}

// round 16
// speedup vs baseline: 1.1351x; 1.1351x over previous
#include <cuda_runtime.h>

#define THREADS 128
#define GPB 16            // graphs per block (8 lane-groups x 2 graphs/thread)

// Output layout: concat of recon[B,4,13,13], mu[B,13,16], logvar[B,13,16] (fp32)
#define R_MU 22151168ull
#define R_LV 28966912ull

typedef unsigned long long u64;

__device__ __forceinline__ void ffma2(u64 &d, u64 a, u64 b) {
    asm("fma.rn.f32x2 %0, %1, %2, %0;" : "+l"(d) : "l"(a), "l"(b));
}
__device__ __forceinline__ u64 ffma2n(u64 a, u64 b, u64 c) {   // a*b + c
    u64 r; asm("fma.rn.f32x2 %0, %1, %2, %3;" : "=l"(r) : "l"(a), "l"(b), "l"(c)); return r;
}
__device__ __forceinline__ u64 pack2(float lo, float hi) {
    u64 r; asm("mov.b64 %0, {%1, %2};" : "=l"(r) : "f"(lo), "f"(hi)); return r;
}
__device__ __forceinline__ float2 unpack2(u64 v) {
    float2 r; asm("mov.b64 {%0, %1}, %2;" : "=f"(r.x), "=f"(r.y) : "l"(v)); return r;
}
__device__ __forceinline__ u64 plo(float4 w) { return pack2(w.x, w.y); }
__device__ __forceinline__ u64 phi(float4 w) { return pack2(w.z, w.w); }
__device__ __forceinline__ float lrelu(float v) { return fmaxf(v, 0.01f * v); }

struct __align__(16) Smem {
    ulonglong2 wt0[256];   // transposed mlp_w0: [l][d][4] pairs over e
    ulonglong2 wt1[256];
    ulonglong2 dect[256];  // transposed dec_w: [k][j][4] pairs over d
    ulonglong2 fct1[64];   // transposed fc1_w: [d][4]
    ulonglong2 fct2[64];
    ulonglong2 b0p[16];    // bias pairs: [l][4]
    ulonglong2 b1p[16];
    ulonglong2 decbp[16];
    ulonglong2 fc1bp[4], fc2bp[4];
    float4 xsv[GPB * 65];  // per-g node rows, pitch 5 float4
    float  adj[GPB * 676]; // per-g [i*169+n*13+m]; reused as recon staging
};

// column-form 16x16 GEMV for 2 graphs: o = bias + sum_d in[d] * Wcol_d (packed pairs)
__device__ __forceinline__ void gemv2(const ulonglong2* __restrict__ wc,
                                      const ulonglong2* __restrict__ bp,
                                      const float* in0, const float* in1,
                                      u64* o0, u64* o1) {
    ulonglong2 bv0 = bp[0], bv1 = bp[1], bv2 = bp[2], bv3 = bp[3];
    o0[0]=bv0.x; o0[1]=bv0.y; o0[2]=bv1.x; o0[3]=bv1.y;
    o0[4]=bv2.x; o0[5]=bv2.y; o0[6]=bv3.x; o0[7]=bv3.y;
#pragma unroll
    for (int q = 0; q < 8; q++) o1[q] = o0[q];
#pragma unroll
    for (int d = 0; d < 16; d++) {
        ulonglong2 w0 = wc[d*4], w1 = wc[d*4+1], w2 = wc[d*4+2], w3 = wc[d*4+3];
        u64 q0 = pack2(in0[d], in0[d]);
        u64 q1 = pack2(in1[d], in1[d]);
        ffma2(o0[0], q0, w0.x); ffma2(o0[1], q0, w0.y);
        ffma2(o0[2], q0, w1.x); ffma2(o0[3], q0, w1.y);
        ffma2(o0[4], q0, w2.x); ffma2(o0[5], q0, w2.y);
        ffma2(o0[6], q0, w3.x); ffma2(o0[7], q0, w3.y);
        ffma2(o1[0], q1, w0.x); ffma2(o1[1], q1, w0.y);
        ffma2(o1[2], q1, w1.x); ffma2(o1[3], q1, w1.y);
        ffma2(o1[4], q1, w2.x); ffma2(o1[5], q1, w2.y);
        ffma2(o1[6], q1, w3.x); ffma2(o1[7], q1, w3.y);
    }
}

__global__ __launch_bounds__(THREADS, 3) void vae_fused(
    const float* __restrict__ adj,
    const float* __restrict__ init_weight,
    const float* __restrict__ eps_param,
    const float* __restrict__ mlp_w0,  const float* __restrict__ mlp_b0,
    const float* __restrict__ mlp_w1,  const float* __restrict__ mlp_b1,
    const float* __restrict__ bn_in_gamma,  const float* __restrict__ bn_in_beta,
    const float* __restrict__ bn_in_mean,   const float* __restrict__ bn_in_var,
    const float* __restrict__ bn_out_gamma, const float* __restrict__ bn_out_beta,
    const float* __restrict__ bn_out_mean,  const float* __restrict__ bn_out_var,
    const float* __restrict__ fc1_w, const float* __restrict__ fc1_b,
    const float* __restrict__ fc2_w, const float* __restrict__ fc2_b,
    const float* __restrict__ dec_w, const float* __restrict__ dec_b,
    float* __restrict__ out)
{
    extern __shared__ Smem sm[];
    Smem& s = sm[0];
    const int tid = threadIdx.x;

    // ---- stage transposed weights: dst[l*256 + col*16 + row] = src[l*256 + row*16 + col]
    for (int idx = tid; idx < 1024; idx += THREADS) {
        int l = idx >> 8, r = idx & 255, row = r >> 4, col = r & 15;
        int di = l*256 + col*16 + row;
        ((float*)s.wt0)[di]  = mlp_w0[idx];
        ((float*)s.wt1)[di]  = mlp_w1[idx];
        ((float*)s.dect)[di] = dec_w[idx];
    }
    for (int idx = tid; idx < 256; idx += THREADS) {
        int row = idx >> 4, col = idx & 15;
        ((float*)s.fct1)[col*16 + row] = fc1_w[idx];
        ((float*)s.fct2)[col*16 + row] = fc2_w[idx];
    }
    if (tid < 64) {
        ((float*)s.b0p)[tid]   = mlp_b0[tid];
        ((float*)s.b1p)[tid]   = mlp_b1[tid];
        ((float*)s.decbp)[tid] = dec_b[tid];
    }
    if (tid < 16) {
        ((float*)s.fc1bp)[tid] = fc1_b[tid];
        ((float*)s.fc2bp)[tid] = fc2_b[tid];
    }
    {   // adj (contiguous float4, coalesced)
        const float4* src = (const float4*)(adj + (size_t)blockIdx.x * (GPB * 676));
        float4* dst = (float4*)s.adj;
        for (int i = tid; i < GPB * 169; i += THREADS) dst[i] = src[i];
    }
    __syncthreads();

    const int grp = tid >> 4;          // 0..7
    const int n   = tid & 15;          // node; lanes 13..15 idle for compute
    const int g0  = grp * 2;
    const size_t b0g = (size_t)blockIdx.x * GPB + g0;
    const float* ad0 = s.adj + g0 * 676;
    const float* ad1 = s.adj + (g0 + 1) * 676;
    float4* xp0 = s.xsv + g0 * 65;
    float4* xp1 = s.xsv + (g0 + 1) * 65;
    const bool act = (n < 13);
    const int nn = act ? n : 0;

    float x0[16], x1[16];

    // ---- init: x[n,:] = sum_m (sum_i adj[i,n,m]) * W[m,:]  (column form over m)
    if (act) {
        float as0[13], as1[13];
#pragma unroll
        for (int m = 0; m < 13; m++) {
            as0[m] = ad0[n*13+m] + ad0[169+n*13+m] + ad0[338+n*13+m] + ad0[507+n*13+m];
            as1[m] = ad1[n*13+m] + ad1[169+n*13+m] + ad1[338+n*13+m] + ad1[507+n*13+m];
        }
        u64 p0[8], p1[8];
#pragma unroll
        for (int q = 0; q < 8; q++) { p0[q] = 0ull; p1[q] = 0ull; }
#pragma unroll
        for (int m = 0; m < 13; m++) {
            const float4* wr = (const float4*)init_weight + m * 4;
            float4 wa = __ldg(wr), wb = __ldg(wr+1), wc = __ldg(wr+2), wd = __ldg(wr+3);
            u64 a0 = pack2(as0[m], as0[m]);
            u64 a1 = pack2(as1[m], as1[m]);
            ffma2(p0[0], a0, plo(wa)); ffma2(p0[1], a0, phi(wa));
            ffma2(p0[2], a0, plo(wb)); ffma2(p0[3], a0, phi(wb));
            ffma2(p0[4], a0, plo(wc)); ffma2(p0[5], a0, phi(wc));
            ffma2(p0[6], a0, plo(wd)); ffma2(p0[7], a0, phi(wd));
            ffma2(p1[0], a1, plo(wa)); ffma2(p1[1], a1, phi(wa));
            ffma2(p1[2], a1, plo(wb)); ffma2(p1[3], a1, phi(wb));
            ffma2(p1[4], a1, plo(wc)); ffma2(p1[5], a1, phi(wc));
            ffma2(p1[6], a1, plo(wd)); ffma2(p1[7], a1, phi(wd));
        }
#pragma unroll
        for (int q = 0; q < 8; q++) {
            float2 f0 = unpack2(p0[q]); x0[2*q] = f0.x; x0[2*q+1] = f0.y;
            float2 f1 = unpack2(p1[q]); x1[2*q] = f1.x; x1[2*q+1] = f1.y;
        }
#pragma unroll
        for (int q = 0; q < 4; q++) {
            xp0[n*5 + q] = make_float4(x0[4*q], x0[4*q+1], x0[4*q+2], x0[4*q+3]);
            xp1[n*5 + q] = make_float4(x1[4*q], x1[4*q+1], x1[4*q+2], x1[4*q+3]);
        }
    }
    __syncwarp();

    // ---- 4 GIN layers ----
#pragma unroll 1
    for (int l = 0; l < 4; l++) {
        const int pi = l * 13 + nn;
        const float si = __ldg(bn_in_gamma + pi)  * rsqrtf(__ldg(bn_in_var + pi)  + 1e-5f);
        const float ti = __ldg(bn_in_beta + pi)   - __ldg(bn_in_mean + pi)  * si;
        const float so = __ldg(bn_out_gamma + pi) * rsqrtf(__ldg(bn_out_var + pi) + 1e-5f);
        const float to = __ldg(bn_out_beta + pi)  - __ldg(bn_out_mean + pi) * so;
        if (act) {
            const float ep = 1.f + __ldg(eps_param + l);
            const u64 si2 = pack2(si, si), ti2 = pack2(ti, ti);
            const u64 so2 = pack2(so, so), to2 = pack2(to, to);
            u64 agg0[8], agg1[8];
#pragma unroll
            for (int q = 0; q < 8; q++) {
                agg0[q] = pack2(ep * x0[2*q], ep * x0[2*q+1]);
                agg1[q] = pack2(ep * x1[2*q], ep * x1[2*q+1]);
            }
#pragma unroll
            for (int i = 0; i < 4; i++) {
                const float* ar0 = ad0 + i*169 + n*13;
                const float* ar1 = ad1 + i*169 + n*13;
#pragma unroll
                for (int m = 0; m < 13; m++) {
                    float v0 = ar0[m], v1 = ar1[m];
                    u64 av0 = pack2(v0, v0), av1 = pack2(v1, v1);
                    float4 xr0 = xp0[m*5 + i];
                    float4 xr1 = xp1[m*5 + i];
                    ffma2(agg0[2*i],     av0, plo(xr0));
                    ffma2(agg0[2*i + 1], av0, phi(xr0));
                    ffma2(agg1[2*i],     av1, plo(xr1));
                    ffma2(agg1[2*i + 1], av1, phi(xr1));
                }
            }
            float ag0[16], ag1[16];
#pragma unroll
            for (int q = 0; q < 8; q++) {
                float2 f0 = unpack2(agg0[q]); ag0[2*q] = f0.x; ag0[2*q+1] = f0.y;
                float2 f1 = unpack2(agg1[q]); ag1[2*q] = f1.x; ag1[2*q+1] = f1.y;
            }
            u64 o0[8], o1[8];
            gemv2(s.wt0 + l*64, s.b0p + l*4, ag0, ag1, o0, o1);
            float hh0[16], hh1[16];
#pragma unroll
            for (int q = 0; q < 8; q++) {
                float2 f0 = unpack2(ffma2n(o0[q], si2, ti2));
                hh0[2*q] = lrelu(f0.x); hh0[2*q+1] = lrelu(f0.y);
                float2 f1 = unpack2(ffma2n(o1[q], si2, ti2));
                hh1[2*q] = lrelu(f1.x); hh1[2*q+1] = lrelu(f1.y);
            }
            gemv2(s.wt1 + l*64, s.b1p + l*4, hh0, hh1, o0, o1);
#pragma unroll
            for (int q = 0; q < 8; q++) {
                float2 f0 = unpack2(ffma2n(o0[q], so2, to2));
                x0[2*q] = lrelu(f0.x); x0[2*q+1] = lrelu(f0.y);
                float2 f1 = unpack2(ffma2n(o1[q], so2, to2));
                x1[2*q] = lrelu(f1.x); x1[2*q+1] = lrelu(f1.y);
            }
        }
        __syncwarp();
        if (act) {
#pragma unroll
            for (int q = 0; q < 4; q++) {
                xp0[n*5 + q] = make_float4(x0[4*q], x0[4*q+1], x0[4*q+2], x0[4*q+3]);
                xp1[n*5 + q] = make_float4(x1[4*q], x1[4*q+1], x1[4*q+2], x1[4*q+3]);
            }
        }
        __syncwarp();
    }

    // ---- heads: mu / logvar (column GEMV + direct STG.128) ----
    float mu0[16], mu1[16];
    if (act) {
        u64 o0[8], o1[8];
        gemv2(s.fct1, s.fc1bp, x0, x1, o0, o1);
#pragma unroll
        for (int q = 0; q < 8; q++) {
            float2 f0 = unpack2(o0[q]); mu0[2*q] = f0.x; mu0[2*q+1] = f0.y;
            float2 f1 = unpack2(o1[q]); mu1[2*q] = f1.x; mu1[2*q+1] = f1.y;
        }
        {
            float4* m0 = (float4*)(out + R_MU + b0g * 208 + (size_t)n * 16);
            float4* m1 = (float4*)(out + R_MU + (b0g + 1) * 208 + (size_t)n * 16);
#pragma unroll
            for (int q = 0; q < 4; q++) {
                m0[q] = make_float4(mu0[4*q], mu0[4*q+1], mu0[4*q+2], mu0[4*q+3]);
                m1[q] = make_float4(mu1[4*q], mu1[4*q+1], mu1[4*q+2], mu1[4*q+3]);
            }
        }
        gemv2(s.fct2, s.fc2bp, x0, x1, o0, o1);
        {
            float4* l0 = (float4*)(out + R_LV + b0g * 208 + (size_t)n * 16);
            float4* l1 = (float4*)(out + R_LV + (b0g + 1) * 208 + (size_t)n * 16);
#pragma unroll
            for (int q = 0; q < 8; q += 2) {
                float2 fa = unpack2(o0[q]), fb = unpack2(o0[q+1]);
                l0[q >> 1] = make_float4(fa.x, fa.y, fb.x, fb.y);
                float2 fc = unpack2(o1[q]), fd = unpack2(o1[q+1]);
                l1[q >> 1] = make_float4(fc.x, fc.y, fd.x, fd.y);
            }
        }
    }

    // ---- decoder: recon staged into the (dead) adj slice, then coalesced out ----
    float* rec0 = (float*)(s.adj + g0 * 676);
    float* rec1 = (float*)(s.adj + (g0 + 1) * 676);

#pragma unroll 1
    for (int k = 0; k < 4; k++) {
        __syncwarp();
        u64 t0p[8], t1p[8];
        if (act) {
            gemv2(s.dect + k*64, s.decbp + k*4, mu0, mu1, t0p, t1p);
#pragma unroll
            for (int q = 0; q < 8; q += 2) {
                float2 fa = unpack2(t0p[q]), fb = unpack2(t0p[q+1]);
                xp0[n*5 + (q >> 1)] = make_float4(fa.x, fa.y, fb.x, fb.y);
                float2 fc = unpack2(t1p[q]), fd = unpack2(t1p[q+1]);
                xp1[n*5 + (q >> 1)] = make_float4(fc.x, fc.y, fd.x, fd.y);
            }
        }
        __syncwarp();
        if (act) {
            float* rr0 = rec0 + k * 169 + n * 13;
            float* rr1 = rec1 + k * 169 + n * 13;
#pragma unroll
            for (int m = 0; m < 13; m++) {
                u64 aA = 0ull, aB = 0ull, bA = 0ull, bB = 0ull;
#pragma unroll
                for (int q = 0; q < 2; q++) {
                    float4 xr0 = xp0[m*5 + q];
                    float4 xr1 = xp1[m*5 + q];
                    ffma2(aA, t0p[2*q],     plo(xr0));
                    ffma2(aA, t0p[2*q + 1], phi(xr0));
                    ffma2(bA, t1p[2*q],     plo(xr1));
                    ffma2(bA, t1p[2*q + 1], phi(xr1));
                }
#pragma unroll
                for (int q = 2; q < 4; q++) {
                    float4 xr0 = xp0[m*5 + q];
                    float4 xr1 = xp1[m*5 + q];
                    ffma2(aB, t0p[2*q],     plo(xr0));
                    ffma2(aB, t0p[2*q + 1], phi(xr0));
                    ffma2(bB, t1p[2*q],     plo(xr1));
                    ffma2(bB, t1p[2*q + 1], phi(xr1));
                }
                float2 fa = unpack2(aA), fb = unpack2(aB);
                float sv0 = (fa.x + fb.x) + (fa.y + fb.y);
                rr0[m] = fmaxf(sv0, 0.f);
                float2 fc = unpack2(bA), fd = unpack2(bB);
                float sv1 = (fc.x + fd.x) + (fc.y + fd.y);
                rr1[m] = fmaxf(sv1, 0.f);
            }
        }
    }
    __syncwarp();
    // coalesced recon writeout: 676 floats = 169 float4 per graph
    {
        const float4* r40 = (const float4*)rec0;
        const float4* r41 = (const float4*)rec1;
        float4* o40 = (float4*)(out + b0g * 676);
        float4* o41 = (float4*)(out + (b0g + 1) * 676);
#pragma unroll
        for (int it = 0; it < 11; it++) {
            int idx = it * 16 + n;               // 0..175, need 0..168
            if (idx < 169) { o40[idx] = r40[idx]; o41[idx] = r41[idx]; }
        }
    }
}

extern "C" void kernel_launch(void* const* d_in, const int* in_sizes, int n_in,
                              void* d_out, int out_size) {
    (void)in_sizes; (void)n_in; (void)out_size;
    cudaFuncSetAttribute(vae_fused, cudaFuncAttributeMaxDynamicSharedMemorySize,
                         (int)sizeof(Smem));
    vae_fused<<<32768 / GPB, THREADS, sizeof(Smem)>>>(
        (const float*)d_in[0],  (const float*)d_in[1],  (const float*)d_in[2],
        (const float*)d_in[3],  (const float*)d_in[4],  (const float*)d_in[5],
        (const float*)d_in[6],  (const float*)d_in[7],  (const float*)d_in[8],
        (const float*)d_in[9],  (const float*)d_in[10], (const float*)d_in[11],
        (const float*)d_in[12], (const float*)d_in[13], (const float*)d_in[14],
        (const float*)d_in[15], (const float*)d_in[16], (const float*)d_in[17],
        (const float*)d_in[18], (const float*)d_in[19], (const float*)d_in[20],
        (float*)d_out);
}